// round 1
// baseline (speedup 1.0000x reference)
#include <cuda_runtime.h>

#define NDAYS  4
#define NHOURS 24
#define NDH    96          // NDAYS*NHOURS
#define NLINKS 2000
#define NPATHS 20000
#define NODS   4000
#define MAXL   64          // max links per path (mean ~10)
#define MAXP   320         // max paths per link (mean ~100)

// ---------------- device scratch (static, allowed) ----------------
__device__ float          g_V[NLINKS][NDH];     // V transposed: [link][dh]
__device__ float          g_vf[NPATHS][NDH];    // path utilities, later overwritten with f
__device__ int            g_plc[NPATHS];        // links-per-path counts
__device__ unsigned short g_pl[NPATHS][MAXL];   // CSC: link ids per path
__device__ int            g_lpc[NLINKS];        // paths-per-link counts
__device__ unsigned short g_lp[NLINKS][MAXP];   // CSR: path ids per link
__device__ int            g_od_start[NODS + 1];

// ---------------- kernel 0: zero counters ----------------
__global__ void k_init() {
    int i = blockIdx.x * blockDim.x + threadIdx.x;
    if (i < NPATHS) g_plc[i] = 0;
    if (i < NLINKS) g_lpc[i] = 0;
}

// ---------------- kernel 1: V[dh,l] = feats . theta + theta_links ----------------
__global__ void k_V(const float* __restrict__ X,
                    const float* __restrict__ theta_raw,
                    const float* __restrict__ theta_links) {
    int idx = blockIdx.x * blockDim.x + threadIdx.x;
    if (idx >= NDH * NLINKS) return;
    int dh = idx / NLINKS;
    int l  = idx - dh * NLINKS;
    float t0 = fminf(theta_raw[0], 0.0f);
    float t1 = fminf(theta_raw[1], 0.0f);
    float t2 = fminf(theta_raw[2], 0.0f);
    float t3 = fminf(theta_raw[3], 0.0f);
    const float* xp = X + ((size_t)dh * NLINKS + l) * 5;
    float v = xp[1] * t0 + xp[2] * t1 + xp[3] * t2 + xp[4] * t3 + theta_links[l];
    g_V[l][dh] = v;
}

// ---------------- kernel 2: scan D (160 MB), build CSC + CSR ----------------
__device__ __forceinline__ void sp_append(int l, int p) {
    int c1 = atomicAdd(&g_plc[p], 1);
    if (c1 < MAXL) g_pl[p][c1] = (unsigned short)l;
    int c2 = atomicAdd(&g_lpc[l], 1);
    if (c2 < MAXP) g_lp[l][c2] = (unsigned short)p;
}

__global__ void k_sparse(const float4* __restrict__ D4) {
    const int n4    = NLINKS * (NPATHS / 4);
    const int pq    = NPATHS / 4;
    int stride = gridDim.x * blockDim.x;
    for (int i = blockIdx.x * blockDim.x + threadIdx.x; i < n4; i += stride) {
        float4 v = D4[i];
        if (v.x == 0.0f && v.y == 0.0f && v.z == 0.0f && v.w == 0.0f) continue;
        int l = i / pq;
        int p = (i - l * pq) * 4;
        if (v.x != 0.0f) sp_append(l, p + 0);
        if (v.y != 0.0f) sp_append(l, p + 1);
        if (v.z != 0.0f) sp_append(l, p + 2);
        if (v.w != 0.0f) sp_append(l, p + 3);
    }
}

// ---------------- kernel 3: od segment boundaries (od_of_path is sorted) ----------------
__global__ void k_odstart(const int* __restrict__ od_of_path) {
    int p = blockIdx.x * blockDim.x + threadIdx.x;
    if (p >= NPATHS) return;
    int od   = od_of_path[p];
    int prev = (p == 0) ? -1 : od_of_path[p - 1];
    for (int o = prev + 1; o <= od; ++o) g_od_start[o] = p;
    if (p == NPATHS - 1) {
        for (int o = od + 1; o <= NODS; ++o) g_od_start[o] = NPATHS;
    }
}

// ---------------- kernel 4: vf[p,dh] = sum over links of path ----------------
__global__ void k_vf() {
    __shared__ unsigned short ls[MAXL];
    __shared__ int scnt;
    int p  = blockIdx.x;
    int dh = threadIdx.x;   // blockDim = 96
    if (dh == 0) scnt = min(g_plc[p], MAXL);
    __syncthreads();
    int cnt = scnt;
    for (int i = dh; i < cnt; i += NDH) ls[i] = g_pl[p][i];
    __syncthreads();
    float acc = 0.0f;
    for (int i = 0; i < cnt; ++i) acc += g_V[ls[i]][dh];
    g_vf[p][dh] = acc;
}

// ---------------- kernel 5: segmented softmax * q, overwrite g_vf with f ----------------
__global__ void k_softmax(const float* __restrict__ q_sqrt) {
    int od = blockIdx.x;
    int dh = threadIdx.x;   // blockDim = 96
    int s = g_od_start[od];
    int e = g_od_start[od + 1];
    if (s >= e) return;
    float m = -3.4e38f;
    for (int p = s; p < e; ++p) m = fmaxf(m, g_vf[p][dh]);
    float sum = 0.0f;
    for (int p = s; p < e; ++p) sum += expf(g_vf[p][dh] - m);
    float qv  = q_sqrt[od];
    qv *= qv;
    float inv = qv / sum;
    for (int p = s; p < e; ++p) g_vf[p][dh] = expf(g_vf[p][dh] - m) * inv;
}

// ---------------- kernel 6: x = relu(sum over paths of link), epilogue, write out ----------------
__global__ void k_out(const float* __restrict__ X,
                      const float* __restrict__ log_alpha,
                      const float* __restrict__ beta_raw,
                      const float* __restrict__ kcap,
                      float* __restrict__ out) {
    __shared__ unsigned short ps[MAXP];
    __shared__ int scnt;
    int l  = blockIdx.x;
    int dh = threadIdx.x;   // blockDim = 96
    if (dh == 0) scnt = min(g_lpc[l], MAXP);
    __syncthreads();
    int cnt = scnt;
    for (int i = dh; i < cnt; i += NDH) ps[i] = g_lp[l][i];
    __syncthreads();
    float acc = 0.0f;
    for (int i = 0; i < cnt; ++i) acc += g_vf[ps[i]][dh];
    float x = fmaxf(acc, 0.0f);

    float alpha = expf(log_alpha[l]);
    float beta  = fminf(fmaxf(beta_raw[l], 1e-12f), 4.0f);
    float tt    = X[((size_t)dh * NLINKS + l) * 5];   // X[...,0]
    float ratio = x / kcap[l];
    out[(size_t)dh * NLINKS + l] = tt * (1.0f + alpha * powf(ratio, beta));
}

// ---------------- launcher ----------------
extern "C" void kernel_launch(void* const* d_in, const int* in_sizes, int n_in,
                              void* d_out, int out_size) {
    const float* X           = (const float*)d_in[0];
    const float* theta_raw   = (const float*)d_in[1];
    const float* theta_links = (const float*)d_in[2];
    const float* q_sqrt      = (const float*)d_in[3];
    const float* log_alpha   = (const float*)d_in[4];
    const float* beta_raw    = (const float*)d_in[5];
    const float* kcap        = (const float*)d_in[6];
    const float* D           = (const float*)d_in[7];
    const int*   od_of_path  = (const int*)d_in[8];
    float*       out         = (float*)d_out;

    k_init<<<(NPATHS + 255) / 256, 256>>>();
    k_V<<<(NDH * NLINKS + 127) / 128, 128>>>(X, theta_raw, theta_links);
    k_sparse<<<2048, 256>>>((const float4*)D);
    k_odstart<<<(NPATHS + 255) / 256, 256>>>(od_of_path);
    k_vf<<<NPATHS, NDH>>>();
    k_softmax<<<NODS, NDH>>>(q_sqrt);
    k_out<<<NLINKS, NDH>>>(X, log_alpha, beta_raw, kcap, out);
}